// round 2
// baseline (speedup 1.0000x reference)
#include <cuda_runtime.h>
#include <cuda_bf16.h>

#define N_NODES 100000
#define N_EDGES 1600000
#define F 64
#define N_PAD 100096  // multiple of 64

// ---------------- scratch (static device globals; no allocs) ----------------
__device__ float g_el[N_NODES];
__device__ float g_er[N_NODES];
__device__ float g_s[N_NODES];      // segment sum of exp(e)
__device__ float g_agg[N_PAD * F];  // unnormalized feature-space aggregation

// ---------------- init: zero agg and s ----------------
__global__ void k_init() {
    int i = blockIdx.x * blockDim.x + threadIdx.x;
    if (i < N_PAD * F) g_agg[i] = 0.0f;
    if (i < N_NODES) g_s[i] = 0.0f;
}

// ---------------- el/er: warp per node ----------------
__global__ void k_elr(const float* __restrict__ feat,
                      const float* __restrict__ al,
                      const float* __restrict__ ar) {
    int t = blockIdx.x * blockDim.x + threadIdx.x;
    int node = t >> 5;
    int lane = t & 31;
    if (node >= N_NODES) return;
    float2 f = *(const float2*)(feat + node * F + lane * 2);
    float2 a = *(const float2*)(al + lane * 2);
    float2 r = *(const float2*)(ar + lane * 2);
    float pl = f.x * a.x + f.y * a.y;
    float pr = f.x * r.x + f.y * r.y;
    #pragma unroll
    for (int off = 16; off; off >>= 1) {
        pl += __shfl_down_sync(0xFFFFFFFFu, pl, off);
        pr += __shfl_down_sync(0xFFFFFFFFu, pr, off);
    }
    if (lane == 0) {
        g_el[node] = pl;
        g_er[node] = pr;
    }
}

// ---------------- fused edge pass: w = exp(leaky(el[s]+er[d]))
// lane 0 of each 16-lane edge group accumulates s[d]; all 16 lanes
// scatter w * feat[src] into agg[dst] via red.global.add.v4.f32.
__global__ void k_scatter(const float* __restrict__ feat,
                          const int* __restrict__ src,
                          const int* __restrict__ dst) {
    int t = blockIdx.x * blockDim.x + threadIdx.x;
    int e = t >> 4;
    int q = t & 15;
    if (e >= N_EDGES) return;
    int s = __ldg(src + e), d = __ldg(dst + e);
    // same-address within the 16-lane group -> broadcast, one L1/L2 request
    float ev = g_el[s] + g_er[d];
    ev = (ev >= 0.0f) ? ev : 0.01f * ev;
    float w = __expf(ev);
    if (q == 0) atomicAdd(&g_s[d], w);
    float4 v = *(const float4*)(feat + s * F + q * 4);
    v.x *= w; v.y *= w; v.z *= w; v.w *= w;
    float* p = g_agg + d * F + q * 4;
    asm volatile("red.global.add.v4.f32 [%0], {%1, %2, %3, %4};"
                 :: "l"(p), "f"(v.x), "f"(v.y), "f"(v.z), "f"(v.w)
                 : "memory");
}

// ---------------- final: out = (agg / s) @ W ----------------
// 64 nodes per block, 256 threads: thread owns output col j = tid&63,
// row-group r = tid>>6 (16 nodes each). W column held in registers.
__global__ void k_gemm(const float* __restrict__ W,
                       float* __restrict__ out) {
    __shared__ float fsh[64 * F];
    int tid = threadIdx.x;
    int j = tid & 63;
    int r = tid >> 6;

    float wj[64];
    #pragma unroll
    for (int k = 0; k < 64; k++) wj[k] = W[k * 64 + j];

    int nb = blockIdx.x * 64;
    float4* fsh4 = (float4*)fsh;
    const float4* a4 = (const float4*)(g_agg + nb * F);
    #pragma unroll
    for (int it = 0; it < 4; it++) fsh4[tid + it * 256] = a4[tid + it * 256];
    __syncthreads();

    #pragma unroll
    for (int i = 0; i < 16; i++) {
        int nl = r * 16 + i;
        int node = nb + nl;
        float acc = 0.0f;
        #pragma unroll
        for (int k4 = 0; k4 < 16; k4++) {
            float4 f = *(const float4*)&fsh[nl * F + k4 * 4];
            acc += f.x * wj[k4 * 4 + 0];
            acc += f.y * wj[k4 * 4 + 1];
            acc += f.z * wj[k4 * 4 + 2];
            acc += f.w * wj[k4 * 4 + 3];
        }
        if (node < N_NODES) {
            float sv = g_s[node];
            float sinv = (sv > 0.0f) ? __frcp_rn(sv) : 0.0f;
            out[node * 64 + j] = acc * sinv;
        }
    }
}

// ---------------- launch ----------------
extern "C" void kernel_launch(void* const* d_in, const int* in_sizes, int n_in,
                              void* d_out, int out_size) {
    const float* feat = (const float*)d_in[0];
    const float* W    = (const float*)d_in[1];
    const float* al   = (const float*)d_in[2];
    const float* ar   = (const float*)d_in[3];
    const int*   src  = (const int*)d_in[4];
    const int*   dst  = (const int*)d_in[5];
    float* out = (float*)d_out;

    k_init<<<(N_PAD * F + 255) / 256, 256>>>();
    k_elr<<<(N_NODES * 32 + 255) / 256, 256>>>(feat, al, ar);
    k_scatter<<<(N_EDGES * 16 + 255) / 256, 256>>>(feat, src, dst);
    k_gemm<<<N_PAD / 64, 256>>>(W, out);
}

// round 3
// speedup vs baseline: 1.0743x; 1.0743x over previous
#include <cuda_runtime.h>
#include <cuda_bf16.h>

#define N_NODES 100000
#define N_EDGES 1600000
#define F 64
#define N_PAD 100096           // multiple of 64
#define SCAN_BS 1024
#define N_SCAN_BLKS ((N_NODES + SCAN_BS - 1) / SCAN_BS)  // 98

// ---------------- scratch ----------------
__device__ float g_el[N_NODES];
__device__ float g_er[N_NODES];
__device__ int   g_cnt[N_NODES];      // in-degree histogram
__device__ int   g_off[N_NODES];      // exclusive prefix (CSR row offsets)
__device__ int   g_cur[N_NODES];      // reorder cursors
__device__ int   g_bsum[N_SCAN_BLKS];
__device__ int   g_boff[N_SCAN_BLKS];
__device__ int   g_esrc[N_EDGES];     // edge srcs sorted by dst
__device__ float g_agg[N_PAD * F];    // normalized feature-space aggregation
                                      // (pad rows never written -> stay 0)

// ---------------- init: zero histogram + cursors ----------------
__global__ void k_init() {
    int i = blockIdx.x * blockDim.x + threadIdx.x;
    if (i < N_NODES) { g_cnt[i] = 0; g_cur[i] = 0; }
}

// ---------------- el/er: warp per node ----------------
__global__ void k_elr(const float* __restrict__ feat,
                      const float* __restrict__ al,
                      const float* __restrict__ ar) {
    int t = blockIdx.x * blockDim.x + threadIdx.x;
    int node = t >> 5;
    int lane = t & 31;
    if (node >= N_NODES) return;
    float2 f = *(const float2*)(feat + node * F + lane * 2);
    float2 a = *(const float2*)(al + lane * 2);
    float2 r = *(const float2*)(ar + lane * 2);
    float pl = f.x * a.x + f.y * a.y;
    float pr = f.x * r.x + f.y * r.y;
    #pragma unroll
    for (int off = 16; off; off >>= 1) {
        pl += __shfl_down_sync(0xFFFFFFFFu, pl, off);
        pr += __shfl_down_sync(0xFFFFFFFFu, pr, off);
    }
    if (lane == 0) { g_el[node] = pl; g_er[node] = pr; }
}

// ---------------- histogram of dst ----------------
__global__ void k_hist(const int* __restrict__ dst) {
    int i = blockIdx.x * blockDim.x + threadIdx.x;
    if (i < N_EDGES) atomicAdd(&g_cnt[dst[i]], 1);
}

// ---------------- scan stage 1: per-block inclusive scan ----------------
__global__ void k_scan1() {
    __shared__ int sm[SCAN_BS];
    int tid = threadIdx.x;
    int i = blockIdx.x * SCAN_BS + tid;
    int v = (i < N_NODES) ? g_cnt[i] : 0;
    sm[tid] = v;
    __syncthreads();
    #pragma unroll
    for (int o = 1; o < SCAN_BS; o <<= 1) {
        int y = (tid >= o) ? sm[tid - o] : 0;
        __syncthreads();
        sm[tid] += y;
        __syncthreads();
    }
    if (i < N_NODES) g_off[i] = sm[tid] - v;   // exclusive
    if (tid == SCAN_BS - 1) g_bsum[blockIdx.x] = sm[tid];
}

// ---------------- scan stage 2: scan the block sums (1 block) ----------------
__global__ void k_scan2() {
    __shared__ int sm[128];
    int tid = threadIdx.x;
    int v = (tid < N_SCAN_BLKS) ? g_bsum[tid] : 0;
    sm[tid] = v;
    __syncthreads();
    #pragma unroll
    for (int o = 1; o < 128; o <<= 1) {
        int y = (tid >= o) ? sm[tid - o] : 0;
        __syncthreads();
        sm[tid] += y;
        __syncthreads();
    }
    if (tid < N_SCAN_BLKS) g_boff[tid] = sm[tid] - v;
}

// ---------------- scan stage 3: add block offsets ----------------
__global__ void k_scan3() {
    int i = blockIdx.x * blockDim.x + threadIdx.x;
    if (i < N_NODES) g_off[i] += g_boff[i >> 10];
}

// ---------------- reorder edges into CSR by dst ----------------
__global__ void k_reorder(const int* __restrict__ src,
                          const int* __restrict__ dst) {
    int i = blockIdx.x * blockDim.x + threadIdx.x;
    if (i >= N_EDGES) return;
    int d = dst[i];
    int pos = g_off[d] + atomicAdd(&g_cur[d], 1);
    g_esrc[pos] = src[i];
}

// ---------------- gather: warp per dst node, no atomics ----------------
__global__ void k_gather(const float* __restrict__ feat) {
    int t = blockIdx.x * blockDim.x + threadIdx.x;
    int d = t >> 5;
    int lane = t & 31;
    if (d >= N_NODES) return;
    int deg = g_cnt[d];
    int base = g_off[d];
    float er_d = g_er[d];

    float2 acc = make_float2(0.0f, 0.0f);
    float wsum = 0.0f;

    for (int c = 0; c < deg; c += 32) {
        int n = min(32, deg - c);
        int s = 0; float w = 0.0f;
        if (lane < n) {
            s = __ldg(g_esrc + base + c + lane);
            float ev = g_el[s] + er_d;
            ev = (ev >= 0.0f) ? ev : 0.01f * ev;
            w = __expf(ev);
        }
        wsum += w;
        int j = 0;
        for (; j + 4 <= n; j += 4) {
            int s0 = __shfl_sync(0xFFFFFFFFu, s, j);
            int s1 = __shfl_sync(0xFFFFFFFFu, s, j + 1);
            int s2 = __shfl_sync(0xFFFFFFFFu, s, j + 2);
            int s3 = __shfl_sync(0xFFFFFFFFu, s, j + 3);
            float w0 = __shfl_sync(0xFFFFFFFFu, w, j);
            float w1 = __shfl_sync(0xFFFFFFFFu, w, j + 1);
            float w2 = __shfl_sync(0xFFFFFFFFu, w, j + 2);
            float w3 = __shfl_sync(0xFFFFFFFFu, w, j + 3);
            float2 f0 = __ldg((const float2*)(feat + s0 * F + lane * 2));
            float2 f1 = __ldg((const float2*)(feat + s1 * F + lane * 2));
            float2 f2 = __ldg((const float2*)(feat + s2 * F + lane * 2));
            float2 f3 = __ldg((const float2*)(feat + s3 * F + lane * 2));
            acc.x += w0 * f0.x; acc.y += w0 * f0.y;
            acc.x += w1 * f1.x; acc.y += w1 * f1.y;
            acc.x += w2 * f2.x; acc.y += w2 * f2.y;
            acc.x += w3 * f3.x; acc.y += w3 * f3.y;
        }
        for (; j < n; j++) {
            int sj = __shfl_sync(0xFFFFFFFFu, s, j);
            float wj = __shfl_sync(0xFFFFFFFFu, w, j);
            float2 f = __ldg((const float2*)(feat + sj * F + lane * 2));
            acc.x += wj * f.x; acc.y += wj * f.y;
        }
    }
    #pragma unroll
    for (int o = 16; o; o >>= 1) wsum += __shfl_xor_sync(0xFFFFFFFFu, wsum, o);
    float sinv = (wsum > 0.0f) ? __frcp_rn(wsum) : 0.0f;
    float2 r = make_float2(acc.x * sinv, acc.y * sinv);
    *(float2*)(g_agg + d * F + lane * 2) = r;
}

// ---------------- GEMM: out = agg @ W ----------------
// 64 rows x 64 cols per block, 256 threads, thread tile 2r x 8c.
// A transposed in smem (pad 66 floats/row, even for float2 alignment).
__global__ void __launch_bounds__(256) k_gemm(const float* __restrict__ W,
                                              float* __restrict__ out) {
    __shared__ float At[64][66];   // At[k][r]
    __shared__ float Ws[64 * 64];  // Ws[k*64 + j]
    int tid = threadIdx.x;
    int tx = tid & 7;        // col group (8 cols)
    int ty = tid >> 3;       // row group (2 rows)
    int nb = blockIdx.x * 64;

    // load + transpose A tile: 1024 float4s
    const float4* a4 = (const float4*)(g_agg + nb * F);
    #pragma unroll
    for (int jj = 0; jj < 4; jj++) {
        int idx = tid + jj * 256;
        int r = idx >> 4;
        int kq = idx & 15;
        float4 v = a4[idx];
        At[kq * 4 + 0][r] = v.x;
        At[kq * 4 + 1][r] = v.y;
        At[kq * 4 + 2][r] = v.z;
        At[kq * 4 + 3][r] = v.w;
    }
    // load W (64x64) straight
    const float4* w4 = (const float4*)W;
    float4* ws4 = (float4*)Ws;
    #pragma unroll
    for (int jj = 0; jj < 4; jj++) ws4[tid + jj * 256] = w4[tid + jj * 256];
    __syncthreads();

    float acc[2][8];
    #pragma unroll
    for (int r = 0; r < 2; r++)
        #pragma unroll
        for (int c = 0; c < 8; c++) acc[r][c] = 0.0f;

    #pragma unroll
    for (int k = 0; k < 64; k++) {
        float2 a = *(const float2*)&At[k][ty * 2];
        float4 w0 = *(const float4*)&Ws[k * 64 + tx * 8];
        float4 w1 = *(const float4*)&Ws[k * 64 + tx * 8 + 4];
        acc[0][0] += a.x * w0.x; acc[0][1] += a.x * w0.y;
        acc[0][2] += a.x * w0.z; acc[0][3] += a.x * w0.w;
        acc[0][4] += a.x * w1.x; acc[0][5] += a.x * w1.y;
        acc[0][6] += a.x * w1.z; acc[0][7] += a.x * w1.w;
        acc[1][0] += a.y * w0.x; acc[1][1] += a.y * w0.y;
        acc[1][2] += a.y * w0.z; acc[1][3] += a.y * w0.w;
        acc[1][4] += a.y * w1.x; acc[1][5] += a.y * w1.y;
        acc[1][6] += a.y * w1.z; acc[1][7] += a.y * w1.w;
    }

    #pragma unroll
    for (int r = 0; r < 2; r++) {
        int node = nb + ty * 2 + r;
        if (node < N_NODES) {
            float* p = out + node * 64 + tx * 8;
            *(float4*)p = make_float4(acc[r][0], acc[r][1], acc[r][2], acc[r][3]);
            *(float4*)(p + 4) = make_float4(acc[r][4], acc[r][5], acc[r][6], acc[r][7]);
        }
    }
}

// ---------------- launch ----------------
extern "C" void kernel_launch(void* const* d_in, const int* in_sizes, int n_in,
                              void* d_out, int out_size) {
    const float* feat = (const float*)d_in[0];
    const float* W    = (const float*)d_in[1];
    const float* al   = (const float*)d_in[2];
    const float* ar   = (const float*)d_in[3];
    const int*   src  = (const int*)d_in[4];
    const int*   dst  = (const int*)d_in[5];
    float* out = (float*)d_out;

    k_init<<<(N_NODES + 255) / 256, 256>>>();
    k_elr<<<(N_NODES * 32 + 255) / 256, 256>>>(feat, al, ar);
    k_hist<<<(N_EDGES + 255) / 256, 256>>>(dst);
    k_scan1<<<N_SCAN_BLKS, SCAN_BS>>>();
    k_scan2<<<1, 128>>>();
    k_scan3<<<(N_NODES + 255) / 256, 256>>>();
    k_reorder<<<(N_EDGES + 255) / 256, 256>>>(src, dst);
    k_gather<<<(N_NODES * 32 + 255) / 256, 256>>>(feat);
    k_gemm<<<N_PAD / 64, 256>>>(W, out);
}

// round 4
// speedup vs baseline: 1.1631x; 1.0826x over previous
#include <cuda_runtime.h>
#include <cuda_fp16.h>

#define N_NODES 100000
#define N_EDGES 1600000
#define F 64
#define N_PAD 100096           // multiple of 64
#define SCAN_BS 1024
#define N_SCAN_BLKS ((N_NODES + SCAN_BS - 1) / SCAN_BS)  // 98

// ---------------- scratch ----------------
__device__ float  g_el[N_NODES];
__device__ float  g_er[N_NODES];
__device__ __half g_feath[N_NODES * F];   // fp16 copy of feat
__device__ int    g_cnt[N_NODES];         // in-degree histogram
__device__ int    g_off[N_NODES];         // exclusive prefix within scan block
__device__ int    g_cur[N_NODES];         // reorder cursors
__device__ int    g_bsum[N_SCAN_BLKS];
__device__ int    g_boff[N_SCAN_BLKS];    // scanned block offsets
__device__ int2   g_epay[N_EDGES];        // {src, w_bits} sorted by dst
__device__ float  g_agg[N_PAD * F];       // normalized feature-space agg
                                          // (pad rows never written -> 0)

// ---------------- init ----------------
__global__ void k_init() {
    int i = blockIdx.x * blockDim.x + threadIdx.x;
    if (i < N_NODES) { g_cnt[i] = 0; g_cur[i] = 0; }
}

// ---------------- el/er + fp16 convert: warp per node ----------------
__global__ void k_elr(const float* __restrict__ feat,
                      const float* __restrict__ al,
                      const float* __restrict__ ar) {
    int t = blockIdx.x * blockDim.x + threadIdx.x;
    int node = t >> 5;
    int lane = t & 31;
    if (node >= N_NODES) return;
    float2 f = *(const float2*)(feat + node * F + lane * 2);
    *(__half2*)(g_feath + node * F + lane * 2) = __floats2half2_rn(f.x, f.y);
    float2 a = *(const float2*)(al + lane * 2);
    float2 r = *(const float2*)(ar + lane * 2);
    float pl = f.x * a.x + f.y * a.y;
    float pr = f.x * r.x + f.y * r.y;
    #pragma unroll
    for (int off = 16; off; off >>= 1) {
        pl += __shfl_down_sync(0xFFFFFFFFu, pl, off);
        pr += __shfl_down_sync(0xFFFFFFFFu, pr, off);
    }
    if (lane == 0) { g_el[node] = pl; g_er[node] = pr; }
}

// ---------------- histogram of dst ----------------
__global__ void k_hist(const int* __restrict__ dst) {
    int i = blockIdx.x * blockDim.x + threadIdx.x;
    if (i < N_EDGES) atomicAdd(&g_cnt[dst[i]], 1);
}

// ---------------- scan stage 1: warp-shfl block scan ----------------
__global__ void k_scan1() {
    __shared__ int wsum[32];
    int tid = threadIdx.x;
    int lane = tid & 31;
    int wid = tid >> 5;
    int i = blockIdx.x * SCAN_BS + tid;
    int orig = (i < N_NODES) ? g_cnt[i] : 0;
    int v = orig;
    #pragma unroll
    for (int o = 1; o < 32; o <<= 1) {
        int y = __shfl_up_sync(0xFFFFFFFFu, v, o);
        if (lane >= o) v += y;
    }
    if (lane == 31) wsum[wid] = v;
    __syncthreads();
    if (wid == 0) {
        int w = wsum[lane];
        #pragma unroll
        for (int o = 1; o < 32; o <<= 1) {
            int y = __shfl_up_sync(0xFFFFFFFFu, w, o);
            if (lane >= o) w += y;
        }
        wsum[lane] = w;
    }
    __syncthreads();
    int incl = v + (wid > 0 ? wsum[wid - 1] : 0);
    if (i < N_NODES) g_off[i] = incl - orig;   // exclusive within block
    if (tid == SCAN_BS - 1) g_bsum[blockIdx.x] = incl;
}

// ---------------- scan stage 2: scan the 98 block sums ----------------
__global__ void k_scan2() {
    __shared__ int sm[128];
    int tid = threadIdx.x;
    int v = (tid < N_SCAN_BLKS) ? g_bsum[tid] : 0;
    sm[tid] = v;
    __syncthreads();
    #pragma unroll
    for (int o = 1; o < 128; o <<= 1) {
        int y = (tid >= o) ? sm[tid - o] : 0;
        __syncthreads();
        sm[tid] += y;
        __syncthreads();
    }
    if (tid < N_SCAN_BLKS) g_boff[tid] = sm[tid] - v;
}

// ---------------- reorder: compute w, scatter {src,w} into CSR ----------------
__global__ void k_reorder(const int* __restrict__ src,
                          const int* __restrict__ dst) {
    int i = blockIdx.x * blockDim.x + threadIdx.x;
    if (i >= N_EDGES) return;
    int d = dst[i];
    int s = src[i];
    float ev = g_el[s] + g_er[d];
    ev = (ev >= 0.0f) ? ev : 0.01f * ev;
    float w = __expf(ev);
    int pos = g_off[d] + g_boff[d >> 10] + atomicAdd(&g_cur[d], 1);
    g_epay[pos] = make_int2(s, __float_as_int(w));
}

// ---------------- gather: warp per dst node, no atomics ----------------
__global__ void k_gather() {
    int t = blockIdx.x * blockDim.x + threadIdx.x;
    int d = t >> 5;
    int lane = t & 31;
    if (d >= N_NODES) return;
    int deg = g_cnt[d];
    int base = g_off[d] + g_boff[d >> 10];

    float2 acc = make_float2(0.0f, 0.0f);
    float wsum = 0.0f;

    for (int c = 0; c < deg; c += 32) {
        int n = min(32, deg - c);
        int2 p = make_int2(0, 0);
        if (lane < n) p = __ldg(g_epay + base + c + lane);
        float w = __int_as_float(p.y);          // 0 for idle lanes
        wsum += w;
        int j = 0;
        for (; j + 8 <= n; j += 8) {
            #pragma unroll
            for (int u = 0; u < 8; u++) {
                int   sj = __shfl_sync(0xFFFFFFFFu, p.x, j + u);
                float wj = __shfl_sync(0xFFFFFFFFu, w,   j + u);
                __half2 h = __ldg((const __half2*)(g_feath + sj * F) + lane);
                float2 f = __half22float2(h);
                acc.x += wj * f.x;
                acc.y += wj * f.y;
            }
        }
        for (; j < n; j++) {
            int   sj = __shfl_sync(0xFFFFFFFFu, p.x, j);
            float wj = __shfl_sync(0xFFFFFFFFu, w,   j);
            __half2 h = __ldg((const __half2*)(g_feath + sj * F) + lane);
            float2 f = __half22float2(h);
            acc.x += wj * f.x;
            acc.y += wj * f.y;
        }
    }
    #pragma unroll
    for (int o = 16; o; o >>= 1) wsum += __shfl_xor_sync(0xFFFFFFFFu, wsum, o);
    float sinv = (wsum > 0.0f) ? __frcp_rn(wsum) : 0.0f;
    *(float2*)(g_agg + d * F + lane * 2) = make_float2(acc.x * sinv, acc.y * sinv);
}

// ---------------- GEMM: out = agg @ W ----------------
__global__ void __launch_bounds__(256) k_gemm(const float* __restrict__ W,
                                              float* __restrict__ out) {
    __shared__ float At[64][66];   // At[k][r]
    __shared__ float Ws[64 * 64];  // Ws[k*64 + j]
    int tid = threadIdx.x;
    int tx = tid & 7;        // col group (8 cols)
    int ty = tid >> 3;       // row group (2 rows)
    int nb = blockIdx.x * 64;

    const float4* a4 = (const float4*)(g_agg + nb * F);
    #pragma unroll
    for (int jj = 0; jj < 4; jj++) {
        int idx = tid + jj * 256;
        int r = idx >> 4;
        int kq = idx & 15;
        float4 v = a4[idx];
        At[kq * 4 + 0][r] = v.x;
        At[kq * 4 + 1][r] = v.y;
        At[kq * 4 + 2][r] = v.z;
        At[kq * 4 + 3][r] = v.w;
    }
    const float4* w4 = (const float4*)W;
    float4* ws4 = (float4*)Ws;
    #pragma unroll
    for (int jj = 0; jj < 4; jj++) ws4[tid + jj * 256] = w4[tid + jj * 256];
    __syncthreads();

    float acc[2][8];
    #pragma unroll
    for (int r = 0; r < 2; r++)
        #pragma unroll
        for (int c = 0; c < 8; c++) acc[r][c] = 0.0f;

    #pragma unroll
    for (int k = 0; k < 64; k++) {
        float2 a = *(const float2*)&At[k][ty * 2];
        float4 w0 = *(const float4*)&Ws[k * 64 + tx * 8];
        float4 w1 = *(const float4*)&Ws[k * 64 + tx * 8 + 4];
        acc[0][0] += a.x * w0.x; acc[0][1] += a.x * w0.y;
        acc[0][2] += a.x * w0.z; acc[0][3] += a.x * w0.w;
        acc[0][4] += a.x * w1.x; acc[0][5] += a.x * w1.y;
        acc[0][6] += a.x * w1.z; acc[0][7] += a.x * w1.w;
        acc[1][0] += a.y * w0.x; acc[1][1] += a.y * w0.y;
        acc[1][2] += a.y * w0.z; acc[1][3] += a.y * w0.w;
        acc[1][4] += a.y * w1.x; acc[1][5] += a.y * w1.y;
        acc[1][6] += a.y * w1.z; acc[1][7] += a.y * w1.w;
    }

    #pragma unroll
    for (int r = 0; r < 2; r++) {
        int node = nb + ty * 2 + r;
        if (node < N_NODES) {
            float* p = out + node * 64 + tx * 8;
            *(float4*)p = make_float4(acc[r][0], acc[r][1], acc[r][2], acc[r][3]);
            *(float4*)(p + 4) = make_float4(acc[r][4], acc[r][5], acc[r][6], acc[r][7]);
        }
    }
}

// ---------------- launch ----------------
extern "C" void kernel_launch(void* const* d_in, const int* in_sizes, int n_in,
                              void* d_out, int out_size) {
    const float* feat = (const float*)d_in[0];
    const float* W    = (const float*)d_in[1];
    const float* al   = (const float*)d_in[2];
    const float* ar   = (const float*)d_in[3];
    const int*   src  = (const int*)d_in[4];
    const int*   dst  = (const int*)d_in[5];
    float* out = (float*)d_out;

    k_init<<<(N_NODES + 255) / 256, 256>>>();
    k_elr<<<(N_NODES * 32 + 255) / 256, 256>>>(feat, al, ar);
    k_hist<<<(N_EDGES + 255) / 256, 256>>>(dst);
    k_scan1<<<N_SCAN_BLKS, SCAN_BS>>>();
    k_scan2<<<1, 128>>>();
    k_reorder<<<(N_EDGES + 255) / 256, 256>>>(src, dst);
    k_gather<<<(N_NODES * 32 + 255) / 256, 256>>>();
    k_gemm<<<N_PAD / 64, 256>>>(W, out);
}

// round 7
// speedup vs baseline: 1.4105x; 1.2127x over previous
#include <cuda_runtime.h>
#include <cuda_fp16.h>
#include <cstdint>

#define N_NODES 100000
#define N_EDGES 1600000
#define F 64
#define N_PAD 100096           // multiple of 64
#define SCAN_BS 1024
#define N_SCAN_BLKS ((N_NODES + SCAN_BS - 1) / SCAN_BS)  // 98

// ---------------- scratch ----------------
__device__ float  g_el[N_NODES];
__device__ float  g_er[N_NODES];
__device__ __half g_feath[N_NODES * F];   // fp16 copy of feat
__device__ int    g_cnt[N_NODES];         // in-degree histogram
__device__ int    g_off[N_NODES];         // exclusive prefix within scan block
__device__ int    g_cur[N_NODES];         // reorder cursors
__device__ int    g_bsum[N_SCAN_BLKS];
__device__ int    g_boff[N_SCAN_BLKS];    // scanned block offsets (written by reorder blk 0)
__device__ int2   g_epay[N_EDGES];        // {src, w_bits} sorted by dst
__device__ float  g_agg[N_PAD * F];       // normalized feature-space agg (pad rows stay 0)

// ---------------- el/er + fp16 convert + zero cnt/cur ----------------
__global__ void k_elr(const float* __restrict__ feat,
                      const float* __restrict__ al,
                      const float* __restrict__ ar) {
    int t = blockIdx.x * blockDim.x + threadIdx.x;
    if (t < N_NODES) { g_cnt[t] = 0; g_cur[t] = 0; }
    int node = t >> 5;
    int lane = t & 31;
    if (node >= N_NODES) return;
    float2 f = *(const float2*)(feat + node * F + lane * 2);
    *(__half2*)(g_feath + node * F + lane * 2) = __floats2half2_rn(f.x, f.y);
    float2 a = *(const float2*)(al + lane * 2);
    float2 r = *(const float2*)(ar + lane * 2);
    float pl = f.x * a.x + f.y * a.y;
    float pr = f.x * r.x + f.y * r.y;
    #pragma unroll
    for (int off = 16; off; off >>= 1) {
        pl += __shfl_down_sync(0xFFFFFFFFu, pl, off);
        pr += __shfl_down_sync(0xFFFFFFFFu, pr, off);
    }
    if (lane == 0) { g_el[node] = pl; g_er[node] = pr; }
}

// ---------------- histogram of dst ----------------
__global__ void k_hist(const int* __restrict__ dst) {
    int i = blockIdx.x * blockDim.x + threadIdx.x;
    if (i < N_EDGES) atomicAdd(&g_cnt[dst[i]], 1);
}

// ---------------- scan stage 1: warp-shfl block scan ----------------
__global__ void k_scan1() {
    __shared__ int wsum[32];
    int tid = threadIdx.x;
    int lane = tid & 31;
    int wid = tid >> 5;
    int i = blockIdx.x * SCAN_BS + tid;
    int orig = (i < N_NODES) ? g_cnt[i] : 0;
    int v = orig;
    #pragma unroll
    for (int o = 1; o < 32; o <<= 1) {
        int y = __shfl_up_sync(0xFFFFFFFFu, v, o);
        if (lane >= o) v += y;
    }
    if (lane == 31) wsum[wid] = v;
    __syncthreads();
    if (wid == 0) {
        int w = wsum[lane];
        #pragma unroll
        for (int o = 1; o < 32; o <<= 1) {
            int y = __shfl_up_sync(0xFFFFFFFFu, w, o);
            if (lane >= o) w += y;
        }
        wsum[lane] = w;
    }
    __syncthreads();
    int incl = v + (wid > 0 ? wsum[wid - 1] : 0);
    if (i < N_NODES) g_off[i] = incl - orig;   // exclusive within block
    if (tid == SCAN_BS - 1) g_bsum[blockIdx.x] = incl;
}

// ---------------- reorder: inline bsum-scan, compute w, scatter CSR ----------------
__global__ void k_reorder(const int* __restrict__ src,
                          const int* __restrict__ dst) {
    __shared__ int sb[128];  // inclusive scan of block sums
    int tid = threadIdx.x;
    if (tid < 128) sb[tid] = (tid < N_SCAN_BLKS) ? g_bsum[tid] : 0;
    __syncthreads();
    #pragma unroll
    for (int o = 1; o < 128; o <<= 1) {
        int y = (tid < 128 && tid >= o) ? sb[tid - o] : 0;
        __syncthreads();
        if (tid < 128) sb[tid] += y;
        __syncthreads();
    }
    if (blockIdx.x == 0 && tid < N_SCAN_BLKS)
        g_boff[tid] = (tid == 0) ? 0 : sb[tid - 1];

    int i = blockIdx.x * blockDim.x + tid;
    if (i >= N_EDGES) return;
    int d = dst[i];
    int s = src[i];
    float ev = g_el[s] + g_er[d];
    ev = (ev >= 0.0f) ? ev : 0.01f * ev;
    float w = __expf(ev);
    int b = d >> 10;
    int boff = (b == 0) ? 0 : sb[b - 1];
    int pos = g_off[d] + boff + atomicAdd(&g_cur[d], 1);
    g_epay[pos] = make_int2(s, __float_as_int(w));
}

// ---------------- gather: warp per dst node, no atomics ----------------
__global__ void k_gather() {
    int t = blockIdx.x * blockDim.x + threadIdx.x;
    int d = t >> 5;
    int lane = t & 31;
    if (d >= N_NODES) return;
    int deg = g_cnt[d];
    int base = g_off[d] + g_boff[d >> 10];

    float2 acc = make_float2(0.0f, 0.0f);
    float wsum = 0.0f;

    for (int c = 0; c < deg; c += 32) {
        int n = min(32, deg - c);
        int2 p = make_int2(0, 0);
        if (lane < n) p = __ldg(g_epay + base + c + lane);
        float w = __int_as_float(p.y);          // 0 for idle lanes
        wsum += w;
        int j = 0;
        for (; j + 8 <= n; j += 8) {
            #pragma unroll
            for (int u = 0; u < 8; u++) {
                int   sj = __shfl_sync(0xFFFFFFFFu, p.x, j + u);
                float wj = __shfl_sync(0xFFFFFFFFu, w,   j + u);
                __half2 h = __ldg((const __half2*)(g_feath + sj * F) + lane);
                float2 f = __half22float2(h);
                acc.x += wj * f.x;
                acc.y += wj * f.y;
            }
        }
        for (; j < n; j++) {
            int   sj = __shfl_sync(0xFFFFFFFFu, p.x, j);
            float wj = __shfl_sync(0xFFFFFFFFu, w,   j);
            __half2 h = __ldg((const __half2*)(g_feath + sj * F) + lane);
            float2 f = __half22float2(h);
            acc.x += wj * f.x;
            acc.y += wj * f.y;
        }
    }
    #pragma unroll
    for (int o = 16; o; o >>= 1) wsum += __shfl_xor_sync(0xFFFFFFFFu, wsum, o);
    float sinv = (wsum > 0.0f) ? __frcp_rn(wsum) : 0.0f;
    *(float2*)(g_agg + d * F + lane * 2) = make_float2(acc.x * sinv, acc.y * sinv);
}

// ---------------- GEMM: out = agg @ W, HMMA fp16 split (hi/lo) ----------------
// block: 64 rows x 64 cols, 128 threads (4 warps, 16 rows each).
// agg, W split into hi+lo fp16; 3 MMAs per tile -> fp32-level accuracy.
__device__ __forceinline__ void mma16816(float* d, const uint32_t* a,
                                         uint32_t b0, uint32_t b1) {
    asm volatile(
        "mma.sync.aligned.m16n8k16.row.col.f32.f16.f16.f32 "
        "{%0,%1,%2,%3}, {%4,%5,%6,%7}, {%8,%9}, {%0,%1,%2,%3};"
        : "+f"(d[0]), "+f"(d[1]), "+f"(d[2]), "+f"(d[3])
        : "r"(a[0]), "r"(a[1]), "r"(a[2]), "r"(a[3]), "r"(b0), "r"(b1));
}

__global__ void __launch_bounds__(128) k_gemm(const float* __restrict__ W,
                                              float* __restrict__ out) {
    __shared__ __half Ahi[64][72];
    __shared__ __half Alo[64][72];
    __shared__ __half Bhi[64][72];   // Wt[n][k]
    __shared__ __half Blo[64][72];
    int tid = threadIdx.x;
    int nb = blockIdx.x * 64;

    // load + split agg tile (64x64 f32 = 1024 float4)
    const float4* a4 = (const float4*)(g_agg + nb * F);
    #pragma unroll
    for (int it = 0; it < 8; it++) {
        int idx = tid + it * 128;
        int r = idx >> 4;
        int c = (idx & 15) * 4;
        float4 v = a4[idx];
        float vv[4] = {v.x, v.y, v.z, v.w};
        #pragma unroll
        for (int j = 0; j < 4; j++) {
            __half h = __float2half_rn(vv[j]);
            Ahi[r][c + j] = h;
            Alo[r][c + j] = __float2half_rn(vv[j] - __half2float(h));
        }
    }
    // load + split + transpose W (row-major [k][n] -> Bt[n][k])
    const float4* w4 = (const float4*)W;
    #pragma unroll
    for (int it = 0; it < 8; it++) {
        int idx = tid + it * 128;
        int k = idx >> 4;
        int c = (idx & 15) * 4;
        float4 v = w4[idx];
        float vv[4] = {v.x, v.y, v.z, v.w};
        #pragma unroll
        for (int j = 0; j < 4; j++) {
            __half h = __float2half_rn(vv[j]);
            Bhi[c + j][k] = h;
            Blo[c + j][k] = __float2half_rn(vv[j] - __half2float(h));
        }
    }
    __syncthreads();

    int wid = tid >> 5, lane = tid & 31;
    int r0 = wid * 16;
    int qr = lane >> 2;      // 0..7
    int qc = lane & 3;       // 0..3

    // preload A fragments for all 4 k-tiles
    uint32_t ahi[4][4], alo[4][4];
    #pragma unroll
    for (int kt = 0; kt < 4; kt++) {
        int kk = kt * 16 + qc * 2;
        ahi[kt][0] = *(const uint32_t*)&Ahi[r0 + qr][kk];
        ahi[kt][1] = *(const uint32_t*)&Ahi[r0 + qr + 8][kk];
        ahi[kt][2] = *(const uint32_t*)&Ahi[r0 + qr][kk + 8];
        ahi[kt][3] = *(const uint32_t*)&Ahi[r0 + qr + 8][kk + 8];
        alo[kt][0] = *(const uint32_t*)&Alo[r0 + qr][kk];
        alo[kt][1] = *(const uint32_t*)&Alo[r0 + qr + 8][kk];
        alo[kt][2] = *(const uint32_t*)&Alo[r0 + qr][kk + 8];
        alo[kt][3] = *(const uint32_t*)&Alo[r0 + qr + 8][kk + 8];
    }

    int row1 = nb + r0 + qr;
    int row2 = row1 + 8;
    #pragma unroll
    for (int nt = 0; nt < 8; nt++) {
        int n0 = nt * 8 + qr;    // B frag column = lane/4
        float acc[4] = {0.0f, 0.0f, 0.0f, 0.0f};
        #pragma unroll
        for (int kt = 0; kt < 4; kt++) {
            int kk = kt * 16 + qc * 2;
            uint32_t bh0 = *(const uint32_t*)&Bhi[n0][kk];
            uint32_t bh1 = *(const uint32_t*)&Bhi[n0][kk + 8];
            uint32_t bl0 = *(const uint32_t*)&Blo[n0][kk];
            uint32_t bl1 = *(const uint32_t*)&Blo[n0][kk + 8];
            mma16816(acc, ahi[kt], bh0, bh1);
            mma16816(acc, ahi[kt], bl0, bl1);
            mma16816(acc, alo[kt], bh0, bh1);
        }
        int col = nt * 8 + qc * 2;
        if (row1 < N_NODES) *(float2*)(out + row1 * 64 + col) = make_float2(acc[0], acc[1]);
        if (row2 < N_NODES) *(float2*)(out + row2 * 64 + col) = make_float2(acc[2], acc[3]);
    }
}

// ---------------- launch ----------------
extern "C" void kernel_launch(void* const* d_in, const int* in_sizes, int n_in,
                              void* d_out, int out_size) {
    const float* feat = (const float*)d_in[0];
    const float* W    = (const float*)d_in[1];
    const float* al   = (const float*)d_in[2];
    const float* ar   = (const float*)d_in[3];
    const int*   src  = (const int*)d_in[4];
    const int*   dst  = (const int*)d_in[5];
    float* out = (float*)d_out;

    k_elr<<<(N_NODES * 32 + 255) / 256, 256>>>(feat, al, ar);
    k_hist<<<(N_EDGES + 255) / 256, 256>>>(dst);
    k_scan1<<<N_SCAN_BLKS, SCAN_BS>>>();
    k_reorder<<<(N_EDGES + 255) / 256, 256>>>(src, dst);   // 4th -> profiled
    k_gather<<<(N_NODES * 32 + 255) / 256, 256>>>();
    k_gemm<<<N_PAD / 64, 128>>>(W, out);
}